// round 2
// baseline (speedup 1.0000x reference)
#include <cuda_runtime.h>
#include <math.h>

#define HEADS   8
#define DHEAD   32
#define HS      48
#define WS      48
#define HWs     (HS * WS)          // 2304
#define WIN     7
#define RAD     3
#define KN      (WIN * WIN)        // 49
#define TX      16
#define TYB     8
#define NTHR    (TX * TYB)         // 128
#define TILE_W  16
#define TILE_H  16
#define CH      16                 // channel chunk per smem stage
#define NCHUNK  (DHEAD / CH)       // 2
#define HALO_W  (TILE_W + 2 * RAD) // 22
#define HALO_H  (TILE_H + 2 * RAD) // 22
#define HPAD    24                 // padded row stride: 2*24 = 48 = 16 mod 32 -> conflict-free
#define HALO_ELEMS (CH * HALO_H * HALO_W)  // 7744

__global__ __launch_bounds__(NTHR)
void natten2d_kernel(const float* __restrict__ q,
                     const float* __restrict__ k,
                     const float* __restrict__ v,
                     float* __restrict__ out)
{
    // 16 ch x 22 rows x 24 (padded) x 4B = 33792 B
    __shared__ float sT[CH][HALO_H][HPAD];

    const int tx = threadIdx.x;
    const int ty = threadIdx.y;
    const int tid = ty * TX + tx;

    const int tileX0 = blockIdx.x * TILE_W;
    const int tileY0 = blockIdx.y * TILE_H;
    const size_t base = (size_t)blockIdx.z * DHEAD * HWs;

    const float* qp = q + base;
    const float* kp = k + base;
    const float* vp = v + base;
    float* op = out + base;

    const int x    = tileX0 + tx;
    const int y0   = tileY0 + 2 * ty;      // this thread's two output rows
    const int y1   = y0 + 1;
    const int pix0 = y0 * WS + x;
    const int pix1 = pix0 + WS;

    float s0[KN], s1[KN];
    #pragma unroll
    for (int n = 0; n < KN; n++) { s0[n] = 0.0f; s1[n] = 0.0f; }

    // ================= pass 1: scores, channel-chunked =================
    for (int cc = 0; cc < NCHUNK; cc++) {
        const int c0 = cc * CH;

        // ---- load K halo chunk (flattened, unrolled for MLP) ----
        const float* kcc = kp + (size_t)c0 * HWs;
        #pragma unroll 4
        for (int i = tid; i < HALO_ELEMS; i += NTHR) {
            int c  = i / (HALO_H * HALO_W);
            int r  = i - c * (HALO_H * HALO_W);
            int hy = r / HALO_W;
            int hx = r - hy * HALO_W;
            int gy = tileY0 + hy - RAD;
            int gx = tileX0 + hx - RAD;
            float val = 0.0f;
            if (gy >= 0 && gy < HS && gx >= 0 && gx < WS)
                val = kcc[c * HWs + gy * WS + gx];
            sT[c][hy][hx] = val;
        }

        // ---- q preload: 32 independent loads, full MLP ----
        float qr0[CH], qr1[CH];
        #pragma unroll
        for (int c = 0; c < CH; c++) {
            qr0[c] = qp[(c0 + c) * HWs + pix0];
            qr1[c] = qp[(c0 + c) * HWs + pix1];
        }
        __syncthreads();

        // ---- accumulate scores: per (c, halo-row) one 7-wide LDS serves both pixels ----
        #pragma unroll 1
        for (int c = 0; c < CH; c++) {
            const float q0 = qr0[c];
            const float q1 = qr1[c];
            #pragma unroll
            for (int dy = 0; dy < 8; dy++) {
                const float* wr = &sT[c][2 * ty + dy][tx];
                float w0 = wr[0], w1 = wr[1], w2 = wr[2], w3 = wr[3],
                      w4 = wr[4], w5 = wr[5], w6 = wr[6];
                if (dy < 7) {   // compile-time
                    const int b = dy * 7;
                    s0[b + 0] = fmaf(q0, w0, s0[b + 0]);
                    s0[b + 1] = fmaf(q0, w1, s0[b + 1]);
                    s0[b + 2] = fmaf(q0, w2, s0[b + 2]);
                    s0[b + 3] = fmaf(q0, w3, s0[b + 3]);
                    s0[b + 4] = fmaf(q0, w4, s0[b + 4]);
                    s0[b + 5] = fmaf(q0, w5, s0[b + 5]);
                    s0[b + 6] = fmaf(q0, w6, s0[b + 6]);
                }
                if (dy > 0) {   // compile-time
                    const int b = (dy - 1) * 7;
                    s1[b + 0] = fmaf(q1, w0, s1[b + 0]);
                    s1[b + 1] = fmaf(q1, w1, s1[b + 1]);
                    s1[b + 2] = fmaf(q1, w2, s1[b + 2]);
                    s1[b + 3] = fmaf(q1, w3, s1[b + 3]);
                    s1[b + 4] = fmaf(q1, w4, s1[b + 4]);
                    s1[b + 5] = fmaf(q1, w5, s1[b + 5]);
                    s1[b + 6] = fmaf(q1, w6, s1[b + 6]);
                }
            }
        }
        __syncthreads();  // done reading this chunk before it is overwritten
    }

    // ================= mask + scale + softmax (registers) =================
    const float scale = 0.17677669529663687f; // 1/sqrt(32)
    float m0 = -1e30f, m1 = -1e30f;
    #pragma unroll
    for (int n = 0; n < KN; n++) {
        const int dy = n / WIN - RAD;
        const int dx = n % WIN - RAD;
        const int gx = x + dx;
        const bool vx = (gx >= 0) & (gx < WS);
        const int gy0 = y0 + dy;
        const int gy1 = y1 + dy;
        const bool v0 = vx & (gy0 >= 0) & (gy0 < HS);
        const bool v1 = vx & (gy1 >= 0) & (gy1 < HS);
        s0[n] = v0 ? s0[n] * scale : -1e30f;
        s1[n] = v1 ? s1[n] * scale : -1e30f;
        m0 = fmaxf(m0, s0[n]);
        m1 = fmaxf(m1, s1[n]);
    }
    float sum0 = 0.0f, sum1 = 0.0f;
    #pragma unroll
    for (int n = 0; n < KN; n++) {
        s0[n] = __expf(s0[n] - m0);
        s1[n] = __expf(s1[n] - m1);
        sum0 += s0[n];
        sum1 += s1[n];
    }
    const float inv0 = 1.0f / sum0;
    const float inv1 = 1.0f / sum1;

    // ================= pass 2: output, channel-chunked =================
    for (int cc = 0; cc < NCHUNK; cc++) {
        const int c0 = cc * CH;

        // ---- load V halo chunk ----
        const float* vcc = vp + (size_t)c0 * HWs;
        #pragma unroll 4
        for (int i = tid; i < HALO_ELEMS; i += NTHR) {
            int c  = i / (HALO_H * HALO_W);
            int r  = i - c * (HALO_H * HALO_W);
            int hy = r / HALO_W;
            int hx = r - hy * HALO_W;
            int gy = tileY0 + hy - RAD;
            int gx = tileX0 + hx - RAD;
            float val = 0.0f;
            if (gy >= 0 && gy < HS && gx >= 0 && gx < WS)
                val = vcc[c * HWs + gy * WS + gx];
            sT[c][hy][hx] = val;
        }
        __syncthreads();

        #pragma unroll 1
        for (int c = 0; c < CH; c++) {
            // 4 accumulator chains per pixel to break the FMA dependency chain
            float a00 = 0.f, a01 = 0.f, a02 = 0.f, a03 = 0.f;
            float a10 = 0.f, a11 = 0.f, a12 = 0.f, a13 = 0.f;
            #pragma unroll
            for (int dy = 0; dy < 8; dy++) {
                const float* wr = &sT[c][2 * ty + dy][tx];
                float w0 = wr[0], w1 = wr[1], w2 = wr[2], w3 = wr[3],
                      w4 = wr[4], w5 = wr[5], w6 = wr[6];
                if (dy < 7) {
                    const int b = dy * 7;
                    a00 = fmaf(s0[b + 0], w0, a00);
                    a01 = fmaf(s0[b + 1], w1, a01);
                    a02 = fmaf(s0[b + 2], w2, a02);
                    a03 = fmaf(s0[b + 3], w3, a03);
                    a00 = fmaf(s0[b + 4], w4, a00);
                    a01 = fmaf(s0[b + 5], w5, a01);
                    a02 = fmaf(s0[b + 6], w6, a02);
                }
                if (dy > 0) {
                    const int b = (dy - 1) * 7;
                    a10 = fmaf(s1[b + 0], w0, a10);
                    a11 = fmaf(s1[b + 1], w1, a11);
                    a12 = fmaf(s1[b + 2], w2, a12);
                    a13 = fmaf(s1[b + 3], w3, a13);
                    a10 = fmaf(s1[b + 4], w4, a10);
                    a11 = fmaf(s1[b + 5], w5, a11);
                    a12 = fmaf(s1[b + 6], w6, a12);
                }
            }
            op[(c0 + c) * HWs + pix0] = ((a00 + a01) + (a02 + a03)) * inv0;
            op[(c0 + c) * HWs + pix1] = ((a10 + a11) + (a12 + a13)) * inv1;
        }
        __syncthreads();  // done reading before next chunk overwrites
    }
}

extern "C" void kernel_launch(void* const* d_in, const int* in_sizes, int n_in,
                              void* d_out, int out_size)
{
    const float* q = (const float*)d_in[0];
    const float* k = (const float*)d_in[1];
    const float* v = (const float*)d_in[2];
    float* o = (float*)d_out;

    const int B = in_sizes[0] / (HEADS * DHEAD * HWs); // 4
    dim3 grid(WS / TILE_W, HS / TILE_H, B * HEADS);    // (3, 3, 32)
    dim3 block(TX, TYB);                               // (16, 8)
    natten2d_kernel<<<grid, block>>>(q, k, v, o);
}

// round 3
// speedup vs baseline: 1.4939x; 1.4939x over previous
#include <cuda_runtime.h>
#include <math.h>

#define HEADS   8
#define DHEAD   32
#define HS      48
#define WS      48
#define HWs     (HS * WS)          // 2304
#define WIN     7
#define RAD     3
#define KN      (WIN * WIN)        // 49
#define TX      16
#define TY      8
#define NTHR    (TX * TY)          // 128
#define HALO_W  (TX + 2 * RAD)     // 22
#define HALO_H  (TY + 2 * RAD)     // 14
#define HPAD    24                 // padded row stride (words)
#define HALO_PIX (HALO_H * HALO_W) // 308
#define HALO_ELEMS (DHEAD * HALO_PIX)  // 9856

__global__ __launch_bounds__(NTHR)
void natten2d_kernel(const float* __restrict__ q,
                     const float* __restrict__ k,
                     const float* __restrict__ v,
                     float* __restrict__ out)
{
    // 32 ch x 14 rows x 24 (padded) words x 4B = 43008 B, reused for K then V
    __shared__ float sT[DHEAD][HALO_H][HPAD];

    const int tx = threadIdx.x;
    const int ty = threadIdx.y;
    const int tid = ty * TX + tx;

    const int tileX0 = blockIdx.x * TX;
    const int tileY0 = blockIdx.y * TY;
    const size_t base = (size_t)blockIdx.z * DHEAD * HWs;

    const float* qp = q + base;
    const float* kp = k + base;
    const float* vp = v + base;
    float* op = out + base;

    const int x = tileX0 + tx;
    const int y = tileY0 + ty;
    const int pix = y * WS + x;

    // ---------------- load K halo: flattened, high MLP, branch-free ----------------
    {
        #pragma unroll 8
        for (int i = tid; i < HALO_ELEMS; i += NTHR) {
            int c  = i / HALO_PIX;
            int r  = i - c * HALO_PIX;
            int hy = r / HALO_W;
            int hx = r - hy * HALO_W;
            int gy = tileY0 + hy - RAD;
            int gx = tileX0 + hx - RAD;
            bool valid = (gy >= 0) & (gy < HS) & (gx >= 0) & (gx < WS);
            int cy = min(max(gy, 0), HS - 1);
            int cx = min(max(gx, 0), WS - 1);
            float val = __ldg(&kp[c * HWs + cy * WS + cx]);   // always issue: full MLP
            sT[c][hy][hx] = valid ? val : 0.0f;
        }
    }

    // prefetch first q batch while halo loads are in flight
    float qa[8];
    #pragma unroll
    for (int j = 0; j < 8; j++) qa[j] = qp[j * HWs + pix];

    __syncthreads();

    // ---------------- pass 1: scores, q software-pipelined in 8-channel batches ----------------
    float sc[KN];
    #pragma unroll
    for (int n = 0; n < KN; n++) sc[n] = 0.0f;

    #pragma unroll 1
    for (int cb = 0; cb < DHEAD; cb += 8) {
        // issue next batch's loads before computing current batch
        float qb[8];
        if (cb + 8 < DHEAD) {
            #pragma unroll
            for (int j = 0; j < 8; j++) qb[j] = qp[(cb + 8 + j) * HWs + pix];
        }
        #pragma unroll
        for (int j = 0; j < 8; j++) {
            const float qc = qa[j];
            const float* kb = &sT[cb + j][ty][tx];
            #pragma unroll
            for (int dy = 0; dy < WIN; dy++) {
                const float* wr = kb + dy * HPAD;
                sc[dy * WIN + 0] = fmaf(qc, wr[0], sc[dy * WIN + 0]);
                sc[dy * WIN + 1] = fmaf(qc, wr[1], sc[dy * WIN + 1]);
                sc[dy * WIN + 2] = fmaf(qc, wr[2], sc[dy * WIN + 2]);
                sc[dy * WIN + 3] = fmaf(qc, wr[3], sc[dy * WIN + 3]);
                sc[dy * WIN + 4] = fmaf(qc, wr[4], sc[dy * WIN + 4]);
                sc[dy * WIN + 5] = fmaf(qc, wr[5], sc[dy * WIN + 5]);
                sc[dy * WIN + 6] = fmaf(qc, wr[6], sc[dy * WIN + 6]);
            }
        }
        #pragma unroll
        for (int j = 0; j < 8; j++) qa[j] = qb[j];
    }

    // ---------------- mask + scale + softmax (registers) ----------------
    const float scale = 0.17677669529663687f; // 1/sqrt(32)
    float m = -1e30f;
    #pragma unroll
    for (int n = 0; n < KN; n++) {
        int gy = y + (n / WIN) - RAD;
        int gx = x + (n % WIN) - RAD;
        bool valid = (gy >= 0) & (gy < HS) & (gx >= 0) & (gx < WS);
        sc[n] = valid ? sc[n] * scale : -1e30f;
        m = fmaxf(m, sc[n]);
    }
    float ssum = 0.0f;
    #pragma unroll
    for (int n = 0; n < KN; n++) {
        sc[n] = __expf(sc[n] - m);
        ssum += sc[n];
    }
    const float inv = 1.0f / ssum;
    #pragma unroll
    for (int n = 0; n < KN; n++) sc[n] *= inv;   // fold normalization into probs

    // ---------------- load V halo (reuse buffer) ----------------
    __syncthreads(); // everyone done reading K tile
    {
        #pragma unroll 8
        for (int i = tid; i < HALO_ELEMS; i += NTHR) {
            int c  = i / HALO_PIX;
            int r  = i - c * HALO_PIX;
            int hy = r / HALO_W;
            int hx = r - hy * HALO_W;
            int gy = tileY0 + hy - RAD;
            int gx = tileX0 + hx - RAD;
            bool valid = (gy >= 0) & (gy < HS) & (gx >= 0) & (gx < WS);
            int cy = min(max(gy, 0), HS - 1);
            int cx = min(max(gx, 0), WS - 1);
            float val = __ldg(&vp[c * HWs + cy * WS + cx]);
            sT[c][hy][hx] = valid ? val : 0.0f;
        }
    }
    __syncthreads();

    // ---------------- pass 2: out = sum_n p_n * v_neighbor ----------------
    #pragma unroll 1
    for (int c = 0; c < DHEAD; c++) {
        const float* vb = &sT[c][ty][tx];
        float a0 = 0.f, a1 = 0.f, a2 = 0.f, a3 = 0.f;
        #pragma unroll
        for (int dy = 0; dy < WIN; dy++) {
            const float* wr = vb + dy * HPAD;
            a0 = fmaf(sc[dy * WIN + 0], wr[0], a0);
            a1 = fmaf(sc[dy * WIN + 1], wr[1], a1);
            a2 = fmaf(sc[dy * WIN + 2], wr[2], a2);
            a3 = fmaf(sc[dy * WIN + 3], wr[3], a3);
            a0 = fmaf(sc[dy * WIN + 4], wr[4], a0);
            a1 = fmaf(sc[dy * WIN + 5], wr[5], a1);
            a2 = fmaf(sc[dy * WIN + 6], wr[6], a2);
        }
        op[c * HWs + pix] = (a0 + a1) + (a2 + a3);
    }
}

extern "C" void kernel_launch(void* const* d_in, const int* in_sizes, int n_in,
                              void* d_out, int out_size)
{
    const float* q = (const float*)d_in[0];
    const float* k = (const float*)d_in[1];
    const float* v = (const float*)d_in[2];
    float* o = (float*)d_out;

    const int B = in_sizes[0] / (HEADS * DHEAD * HWs); // 4
    dim3 grid(WS / TX, HS / TY, B * HEADS);            // (3, 6, 32) = 576 CTAs
    dim3 block(TX, TY);                                // (16, 8)
    natten2d_kernel<<<grid, block>>>(q, k, v, o);
}

// round 4
// speedup vs baseline: 2.5513x; 1.7078x over previous
#include <cuda_runtime.h>
#include <math.h>

#define HEADS   8
#define DHEAD   32
#define HS      48
#define WS      48
#define HWs     (HS * WS)          // 2304
#define WIN     7
#define RAD     3
#define KN      (WIN * WIN)        // 49
#define TX      16
#define TY      8
#define NTHR    (TX * TY)          // 128
#define HALO_W  (TX + 2 * RAD)     // 22
#define HALO_H  (TY + 2 * RAD)     // 14
#define HPAD    24                 // padded row stride (words)
#define HALO_PIX (HALO_H * HALO_W) // 308

__global__ __launch_bounds__(NTHR, 4)
void natten2d_kernel(const float* __restrict__ q,
                     const float* __restrict__ k,
                     const float* __restrict__ v,
                     float* __restrict__ out)
{
    // 32 ch x 14 rows x 24 (padded) words x 4B = 43008 B, reused for K then V
    __shared__ float sT[DHEAD][HALO_H][HPAD];

    const int tid = threadIdx.x;

    // Row-swizzled mapping: warp w covers rows {base, base+2} so the two
    // half-warps' smem row offsets differ by 2*HPAD = 48 words = 16 banks
    // -> every windowed LDS is bank-conflict-free.
    const int w    = tid >> 5;
    const int l16  = (tid >> 4) & 1;
    const int tx   = tid & 15;
    const int tyS  = ((w >> 1) << 2) + (w & 1) + (l16 << 1);  // 0..7, bijective

    const int tileX0 = blockIdx.x * TX;
    const int tileY0 = blockIdx.y * TY;
    const size_t base = (size_t)blockIdx.z * DHEAD * HWs;

    const float* qp = q + base;
    const float* kp = k + base;
    const float* vp = v + base;
    float* op = out + base;

    const int x = tileX0 + tx;
    const int y = tileY0 + tyS;
    const int pix = y * WS + x;

    // ---------------- load K halo: pixel-outer, channel-unrolled (MLP=32) ----------------
    #pragma unroll
    for (int p0 = 0; p0 < HALO_PIX; p0 += NTHR) {
        const int p = p0 + tid;
        if (p < HALO_PIX) {
            const int hy = p / HALO_W;
            const int hx = p - hy * HALO_W;
            const int gy = tileY0 + hy - RAD;
            const int gx = tileX0 + hx - RAD;
            const bool valid = (gy >= 0) & (gy < HS) & (gx >= 0) & (gx < WS);
            const int src = min(max(gy, 0), HS - 1) * WS + min(max(gx, 0), WS - 1);
            const float* kc = kp + src;
            #pragma unroll
            for (int c = 0; c < DHEAD; c++) {
                float val = __ldg(kc + c * HWs);
                sT[c][hy][hx] = valid ? val : 0.0f;
            }
        }
    }

    // prefetch first q batch while halo loads are in flight
    float qa[8];
    #pragma unroll
    for (int j = 0; j < 8; j++) qa[j] = qp[j * HWs + pix];

    __syncthreads();

    // ---------------- pass 1: scores, q software-pipelined in 8-channel batches ----------------
    float sc[KN];
    #pragma unroll
    for (int n = 0; n < KN; n++) sc[n] = 0.0f;

    #pragma unroll 1
    for (int cb = 0; cb < DHEAD; cb += 8) {
        float qb[8];
        if (cb + 8 < DHEAD) {
            #pragma unroll
            for (int j = 0; j < 8; j++) qb[j] = qp[(cb + 8 + j) * HWs + pix];
        }
        #pragma unroll
        for (int j = 0; j < 8; j++) {
            const float qc = qa[j];
            const float* kb = &sT[cb + j][tyS][tx];
            #pragma unroll
            for (int dy = 0; dy < WIN; dy++) {
                const float* wr = kb + dy * HPAD;
                sc[dy * WIN + 0] = fmaf(qc, wr[0], sc[dy * WIN + 0]);
                sc[dy * WIN + 1] = fmaf(qc, wr[1], sc[dy * WIN + 1]);
                sc[dy * WIN + 2] = fmaf(qc, wr[2], sc[dy * WIN + 2]);
                sc[dy * WIN + 3] = fmaf(qc, wr[3], sc[dy * WIN + 3]);
                sc[dy * WIN + 4] = fmaf(qc, wr[4], sc[dy * WIN + 4]);
                sc[dy * WIN + 5] = fmaf(qc, wr[5], sc[dy * WIN + 5]);
                sc[dy * WIN + 6] = fmaf(qc, wr[6], sc[dy * WIN + 6]);
            }
        }
        #pragma unroll
        for (int j = 0; j < 8; j++) qa[j] = qb[j];
    }

    // ---------------- mask + scale + softmax (registers) ----------------
    const float scale = 0.17677669529663687f; // 1/sqrt(32)
    float m = -1e30f;
    #pragma unroll
    for (int n = 0; n < KN; n++) {
        int gy = y + (n / WIN) - RAD;
        int gx = x + (n % WIN) - RAD;
        bool valid = (gy >= 0) & (gy < HS) & (gx >= 0) & (gx < WS);
        sc[n] = valid ? sc[n] * scale : -1e30f;
        m = fmaxf(m, sc[n]);
    }
    float ssum = 0.0f;
    #pragma unroll
    for (int n = 0; n < KN; n++) {
        sc[n] = __expf(sc[n] - m);
        ssum += sc[n];
    }
    const float inv = 1.0f / ssum;
    #pragma unroll
    for (int n = 0; n < KN; n++) sc[n] *= inv;   // fold normalization into probs

    // ---------------- load V halo (reuse buffer) ----------------
    __syncthreads(); // everyone done reading K tile
    #pragma unroll
    for (int p0 = 0; p0 < HALO_PIX; p0 += NTHR) {
        const int p = p0 + tid;
        if (p < HALO_PIX) {
            const int hy = p / HALO_W;
            const int hx = p - hy * HALO_W;
            const int gy = tileY0 + hy - RAD;
            const int gx = tileX0 + hx - RAD;
            const bool valid = (gy >= 0) & (gy < HS) & (gx >= 0) & (gx < WS);
            const int src = min(max(gy, 0), HS - 1) * WS + min(max(gx, 0), WS - 1);
            const float* vc = vp + src;
            #pragma unroll
            for (int c = 0; c < DHEAD; c++) {
                float val = __ldg(vc + c * HWs);
                sT[c][hy][hx] = valid ? val : 0.0f;
            }
        }
    }
    __syncthreads();

    // ---------------- pass 2: out = sum_n p_n * v_neighbor ----------------
    #pragma unroll 1
    for (int c = 0; c < DHEAD; c++) {
        const float* vb = &sT[c][tyS][tx];
        float a0 = 0.f, a1 = 0.f, a2 = 0.f, a3 = 0.f;
        #pragma unroll
        for (int dy = 0; dy < WIN; dy++) {
            const float* wr = vb + dy * HPAD;
            a0 = fmaf(sc[dy * WIN + 0], wr[0], a0);
            a1 = fmaf(sc[dy * WIN + 1], wr[1], a1);
            a2 = fmaf(sc[dy * WIN + 2], wr[2], a2);
            a3 = fmaf(sc[dy * WIN + 3], wr[3], a3);
            a0 = fmaf(sc[dy * WIN + 4], wr[4], a0);
            a1 = fmaf(sc[dy * WIN + 5], wr[5], a1);
            a2 = fmaf(sc[dy * WIN + 6], wr[6], a2);
        }
        op[c * HWs + pix] = (a0 + a1) + (a2 + a3);
    }
}

extern "C" void kernel_launch(void* const* d_in, const int* in_sizes, int n_in,
                              void* d_out, int out_size)
{
    const float* q = (const float*)d_in[0];
    const float* k = (const float*)d_in[1];
    const float* v = (const float*)d_in[2];
    float* o = (float*)d_out;

    const int B = in_sizes[0] / (HEADS * DHEAD * HWs); // 4
    dim3 grid(WS / TX, HS / TY, B * HEADS);            // (3, 6, 32) = 576 CTAs
    dim3 block(NTHR);                                  // 128 linear
    natten2d_kernel<<<grid, block>>>(q, k, v, o);
}

// round 5
// speedup vs baseline: 3.4698x; 1.3600x over previous
#include <cuda_runtime.h>
#include <math.h>

#define HEADS   8
#define DHEAD   32
#define HS      48
#define WS      48
#define HWs     (HS * WS)          // 2304
#define WIN     7
#define RAD     3
#define KN      (WIN * WIN)        // 49
#define TILE    16                 // 16x16 pixel tile, 2 rows per thread
#define NTHR    128
#define HALO    (TILE + 2 * RAD)   // 22
#define HPAD    24                 // padded row stride (words)
#define CH      16                 // channels per smem stage
#define NCHUNK  (DHEAD / CH)       // 2
#define HALO_PIX (HALO * HALO)     // 484

__global__ __launch_bounds__(NTHR, 2)
void natten2d_kernel(const float* __restrict__ q,
                     const float* __restrict__ k,
                     const float* __restrict__ v,
                     float* __restrict__ out)
{
    // 16 ch x 22 rows x 24 (padded) words x 4B = 33792 B, reused K then V
    __shared__ float sT[CH][HALO][HPAD];

    const int tid = threadIdx.x;
    const int tx  = tid & 15;
    const int typ = tid >> 4;            // 0..7 -> rows {2typ, 2typ+1}
    // lanes 0-15 vs 16-31 differ by 1 in typ -> smem row offset 2*HPAD = 48
    // words = 16 banks -> every windowed LDS conflict-free.

    const int tileX0 = blockIdx.x * TILE;
    const int tileY0 = blockIdx.y * TILE;
    const size_t base = (size_t)blockIdx.z * DHEAD * HWs;

    const float* qp = q + base;
    const float* kp = k + base;
    const float* vp = v + base;
    float* op = out + base;

    const int x    = tileX0 + tx;
    const int y0   = tileY0 + 2 * typ;
    const int y1   = y0 + 1;
    const int pix0 = y0 * WS + x;
    const int pix1 = pix0 + WS;

    float s0[KN], s1[KN];
    #pragma unroll
    for (int n = 0; n < KN; n++) { s0[n] = 0.0f; s1[n] = 0.0f; }

    // ================= pass 1: scores, channel-chunked =================
    #pragma unroll 1
    for (int cc = 0; cc < NCHUNK; cc++) {
        const int c0 = cc * CH;
        const float* kcc = kp + (size_t)c0 * HWs;

        // ---- K halo chunk: pixel-outer, channel-inner (MLP=16), branch-free ----
        #pragma unroll
        for (int p0 = 0; p0 < HALO_PIX; p0 += NTHR) {
            const int p = p0 + tid;
            if (p < HALO_PIX) {
                const int hy = p / HALO;
                const int hx = p - hy * HALO;
                const int gy = tileY0 + hy - RAD;
                const int gx = tileX0 + hx - RAD;
                const bool valid = (gy >= 0) & (gy < HS) & (gx >= 0) & (gx < WS);
                const int src = min(max(gy, 0), HS - 1) * WS + min(max(gx, 0), WS - 1);
                #pragma unroll
                for (int c = 0; c < CH; c++) {
                    float val = __ldg(kcc + c * HWs + src);
                    sT[c][hy][hx] = valid ? val : 0.0f;
                }
            }
        }

        // prefetch first q batch (4 ch x 2 px) while halo loads are in flight
        float qa0[4], qa1[4];
        #pragma unroll
        for (int j = 0; j < 4; j++) {
            qa0[j] = qp[(c0 + j) * HWs + pix0];
            qa1[j] = qp[(c0 + j) * HWs + pix1];
        }
        __syncthreads();

        #pragma unroll 1
        for (int cb = 0; cb < CH; cb += 4) {
            float qb0[4], qb1[4];
            if (cb + 4 < CH) {
                #pragma unroll
                for (int j = 0; j < 4; j++) {
                    qb0[j] = qp[(c0 + cb + 4 + j) * HWs + pix0];
                    qb1[j] = qp[(c0 + cb + 4 + j) * HWs + pix1];
                }
            }
            #pragma unroll
            for (int j = 0; j < 4; j++) {
                const float q0 = qa0[j];
                const float q1 = qa1[j];
                const float* kb = &sT[cb + j][2 * typ][tx];
                #pragma unroll
                for (int r = 0; r < 8; r++) {
                    const float* wr = kb + r * HPAD;
                    const float w0 = wr[0], w1 = wr[1], w2 = wr[2], w3 = wr[3],
                                w4 = wr[4], w5 = wr[5], w6 = wr[6];
                    if (r < 7) {   // compile-time
                        const int b = r * 7;
                        s0[b + 0] = fmaf(q0, w0, s0[b + 0]);
                        s0[b + 1] = fmaf(q0, w1, s0[b + 1]);
                        s0[b + 2] = fmaf(q0, w2, s0[b + 2]);
                        s0[b + 3] = fmaf(q0, w3, s0[b + 3]);
                        s0[b + 4] = fmaf(q0, w4, s0[b + 4]);
                        s0[b + 5] = fmaf(q0, w5, s0[b + 5]);
                        s0[b + 6] = fmaf(q0, w6, s0[b + 6]);
                    }
                    if (r > 0) {   // compile-time
                        const int b = (r - 1) * 7;
                        s1[b + 0] = fmaf(q1, w0, s1[b + 0]);
                        s1[b + 1] = fmaf(q1, w1, s1[b + 1]);
                        s1[b + 2] = fmaf(q1, w2, s1[b + 2]);
                        s1[b + 3] = fmaf(q1, w3, s1[b + 3]);
                        s1[b + 4] = fmaf(q1, w4, s1[b + 4]);
                        s1[b + 5] = fmaf(q1, w5, s1[b + 5]);
                        s1[b + 6] = fmaf(q1, w6, s1[b + 6]);
                    }
                }
            }
            #pragma unroll
            for (int j = 0; j < 4; j++) { qa0[j] = qb0[j]; qa1[j] = qb1[j]; }
        }
        __syncthreads();  // done reading chunk before overwrite
    }

    // ================= mask + scale + softmax (registers, both rows) =================
    const float scale = 0.17677669529663687f; // 1/sqrt(32)
    float m0 = -1e30f, m1 = -1e30f;
    #pragma unroll
    for (int n = 0; n < KN; n++) {
        const int dy = n / WIN - RAD;
        const int dx = n % WIN - RAD;
        const int gx = x + dx;
        const bool vx = (gx >= 0) & (gx < WS);
        const int gy0 = y0 + dy;
        const int gy1 = y1 + dy;
        const bool v0 = vx & (gy0 >= 0) & (gy0 < HS);
        const bool v1 = vx & (gy1 >= 0) & (gy1 < HS);
        s0[n] = v0 ? s0[n] * scale : -1e30f;
        s1[n] = v1 ? s1[n] * scale : -1e30f;
        m0 = fmaxf(m0, s0[n]);
        m1 = fmaxf(m1, s1[n]);
    }
    float sum0 = 0.0f, sum1 = 0.0f;
    #pragma unroll
    for (int n = 0; n < KN; n++) {
        s0[n] = __expf(s0[n] - m0);
        s1[n] = __expf(s1[n] - m1);
        sum0 += s0[n];
        sum1 += s1[n];
    }
    const float inv0 = 1.0f / sum0;
    const float inv1 = 1.0f / sum1;
    #pragma unroll
    for (int n = 0; n < KN; n++) { s0[n] *= inv0; s1[n] *= inv1; }

    // ================= pass 2: output, channel-chunked =================
    #pragma unroll 1
    for (int cc = 0; cc < NCHUNK; cc++) {
        const int c0 = cc * CH;
        const float* vcc = vp + (size_t)c0 * HWs;

        #pragma unroll
        for (int p0 = 0; p0 < HALO_PIX; p0 += NTHR) {
            const int p = p0 + tid;
            if (p < HALO_PIX) {
                const int hy = p / HALO;
                const int hx = p - hy * HALO;
                const int gy = tileY0 + hy - RAD;
                const int gx = tileX0 + hx - RAD;
                const bool valid = (gy >= 0) & (gy < HS) & (gx >= 0) & (gx < WS);
                const int src = min(max(gy, 0), HS - 1) * WS + min(max(gx, 0), WS - 1);
                #pragma unroll
                for (int c = 0; c < CH; c++) {
                    float val = __ldg(vcc + c * HWs + src);
                    sT[c][hy][hx] = valid ? val : 0.0f;
                }
            }
        }
        __syncthreads();

        #pragma unroll 1
        for (int c = 0; c < CH; c++) {
            const float* vb = &sT[c][2 * typ][tx];
            float a0 = 0.f, a1 = 0.f, a2 = 0.f, a3 = 0.f;
            float b0 = 0.f, b1 = 0.f, b2 = 0.f, b3 = 0.f;
            #pragma unroll
            for (int r = 0; r < 8; r++) {
                const float* wr = vb + r * HPAD;
                const float w0 = wr[0], w1 = wr[1], w2 = wr[2], w3 = wr[3],
                            w4 = wr[4], w5 = wr[5], w6 = wr[6];
                if (r < 7) {
                    const int n = r * 7;
                    a0 = fmaf(s0[n + 0], w0, a0);
                    a1 = fmaf(s0[n + 1], w1, a1);
                    a2 = fmaf(s0[n + 2], w2, a2);
                    a3 = fmaf(s0[n + 3], w3, a3);
                    a0 = fmaf(s0[n + 4], w4, a0);
                    a1 = fmaf(s0[n + 5], w5, a1);
                    a2 = fmaf(s0[n + 6], w6, a2);
                }
                if (r > 0) {
                    const int n = (r - 1) * 7;
                    b0 = fmaf(s1[n + 0], w0, b0);
                    b1 = fmaf(s1[n + 1], w1, b1);
                    b2 = fmaf(s1[n + 2], w2, b2);
                    b3 = fmaf(s1[n + 3], w3, b3);
                    b0 = fmaf(s1[n + 4], w4, b0);
                    b1 = fmaf(s1[n + 5], w5, b1);
                    b2 = fmaf(s1[n + 6], w6, b2);
                }
            }
            op[(c0 + c) * HWs + pix0] = (a0 + a1) + (a2 + a3);
            op[(c0 + c) * HWs + pix1] = (b0 + b1) + (b2 + b3);
        }
        __syncthreads();
    }
}

extern "C" void kernel_launch(void* const* d_in, const int* in_sizes, int n_in,
                              void* d_out, int out_size)
{
    const float* q = (const float*)d_in[0];
    const float* k = (const float*)d_in[1];
    const float* v = (const float*)d_in[2];
    float* o = (float*)d_out;

    const int B = in_sizes[0] / (HEADS * DHEAD * HWs); // 4
    dim3 grid(WS / TILE, HS / TILE, B * HEADS);        // (3, 3, 32) = 288
    dim3 block(NTHR);                                  // 128 linear
    natten2d_kernel<<<grid, block>>>(q, k, v, o);
}

// round 6
// speedup vs baseline: 3.7320x; 1.0756x over previous
#include <cuda_runtime.h>
#include <math.h>

#define HEADS   8
#define DHEAD   32
#define HS      48
#define WS      48
#define HWs     (HS * WS)          // 2304
#define WIN     7
#define RAD     3
#define KN      (WIN * WIN)        // 49
#define TILE    16                 // 16x16 pixel tile, 2 rows per thread
#define NTHR    128
#define HALO    (TILE + 2 * RAD)   // 22
#define HPAD2   24                 // padded row stride in float2 elems
#define CP      8                  // channel-PAIRS per smem stage (16 scalar ch)
#define NCHUNK  2                  // 2 stages x 16 ch = 32
#define HALO_PIX (HALO * HALO)     // 484

typedef unsigned long long ull;

__device__ __forceinline__ ull pack2(float lo, float hi) {
    ull r;
    asm("mov.b64 %0, {%1, %2};" : "=l"(r) : "f"(lo), "f"(hi));
    return r;
}
__device__ __forceinline__ void unpack2(ull v, float& lo, float& hi) {
    asm("mov.b64 {%0, %1}, %2;" : "=f"(lo), "=f"(hi) : "l"(v));
}
__device__ __forceinline__ void ffma2(ull& acc, ull a, ull b) {
    asm("fma.rn.f32x2 %0, %1, %2, %3;" : "=l"(acc) : "l"(a), "l"(b), "l"(acc));
}
__device__ __forceinline__ ull add2(ull a, ull b) {
    ull r;
    asm("add.rn.f32x2 %0, %1, %2;" : "=l"(r) : "l"(a), "l"(b));
    return r;
}

__global__ __launch_bounds__(NTHR, 2)
void natten2d_kernel(const float* __restrict__ q,
                     const float* __restrict__ k,
                     const float* __restrict__ v,
                     float* __restrict__ out)
{
    // 8 chan-pairs x 22 rows x 24 float2 x 8B = 33792 B, reused K then V
    __shared__ float2 sT[CP][HALO][HPAD2];

    const int tid = threadIdx.x;
    const int tx  = tid & 15;
    const int typ = tid >> 4;            // 0..7 -> rows {2typ, 2typ+1}

    const int tileX0 = blockIdx.x * TILE;
    const int tileY0 = blockIdx.y * TILE;
    const size_t base = (size_t)blockIdx.z * DHEAD * HWs;

    const float* qp = q + base;
    const float* kp = k + base;
    const float* vp = v + base;
    float* op = out + base;

    const int x    = tileX0 + tx;
    const int y0   = tileY0 + 2 * typ;
    const int y1   = y0 + 1;
    const int pix0 = y0 * WS + x;
    const int pix1 = pix0 + WS;

    // packed accumulators: lo = even channel partial, hi = odd channel partial
    ull s0[KN], s1[KN];
    #pragma unroll
    for (int n = 0; n < KN; n++) { s0[n] = 0ULL; s1[n] = 0ULL; }

    // ================= pass 1: scores, channel-pair chunked =================
    #pragma unroll 1
    for (int cc = 0; cc < NCHUNK; cc++) {
        const int c0 = cc * 2 * CP;                 // scalar channel base
        const float* kcc = kp + (size_t)c0 * HWs;

        // ---- K halo chunk: pixel-outer, pair-inner, branch-free ----
        #pragma unroll
        for (int p0 = 0; p0 < HALO_PIX; p0 += NTHR) {
            const int p = p0 + tid;
            if (p < HALO_PIX) {
                const int hy = p / HALO;
                const int hx = p - hy * HALO;
                const int gy = tileY0 + hy - RAD;
                const int gx = tileX0 + hx - RAD;
                const bool valid = (gy >= 0) & (gy < HS) & (gx >= 0) & (gx < WS);
                const int src = min(max(gy, 0), HS - 1) * WS + min(max(gx, 0), WS - 1);
                #pragma unroll
                for (int cpi = 0; cpi < CP; cpi++) {
                    float v0 = __ldg(kcc + (2 * cpi + 0) * HWs + src);
                    float v1 = __ldg(kcc + (2 * cpi + 1) * HWs + src);
                    sT[cpi][hy][hx] = valid ? make_float2(v0, v1)
                                            : make_float2(0.0f, 0.0f);
                }
            }
        }

        // prefetch first q pair while halo loads are in flight
        ull qa0 = pack2(qp[c0 * HWs + pix0], qp[(c0 + 1) * HWs + pix0]);
        ull qa1 = pack2(qp[c0 * HWs + pix1], qp[(c0 + 1) * HWs + pix1]);
        __syncthreads();

        #pragma unroll 1
        for (int cpi = 0; cpi < CP; cpi++) {
            ull qb0 = 0, qb1 = 0;
            if (cpi + 1 < CP) {
                const int cn = c0 + 2 * (cpi + 1);
                qb0 = pack2(qp[cn * HWs + pix0], qp[(cn + 1) * HWs + pix0]);
                qb1 = pack2(qp[cn * HWs + pix1], qp[(cn + 1) * HWs + pix1]);
            }
            const float2* kb = &sT[cpi][2 * typ][tx];
            #pragma unroll
            for (int r = 0; r < 8; r++) {
                const float2* wr = kb + r * HPAD2;
                ull w0 = *(const ull*)(wr + 0);
                ull w1 = *(const ull*)(wr + 1);
                ull w2 = *(const ull*)(wr + 2);
                ull w3 = *(const ull*)(wr + 3);
                ull w4 = *(const ull*)(wr + 4);
                ull w5 = *(const ull*)(wr + 5);
                ull w6 = *(const ull*)(wr + 6);
                if (r < 7) {   // compile-time
                    const int b = r * 7;
                    ffma2(s0[b + 0], qa0, w0);
                    ffma2(s0[b + 1], qa0, w1);
                    ffma2(s0[b + 2], qa0, w2);
                    ffma2(s0[b + 3], qa0, w3);
                    ffma2(s0[b + 4], qa0, w4);
                    ffma2(s0[b + 5], qa0, w5);
                    ffma2(s0[b + 6], qa0, w6);
                }
                if (r > 0) {   // compile-time
                    const int b = (r - 1) * 7;
                    ffma2(s1[b + 0], qa1, w0);
                    ffma2(s1[b + 1], qa1, w1);
                    ffma2(s1[b + 2], qa1, w2);
                    ffma2(s1[b + 3], qa1, w3);
                    ffma2(s1[b + 4], qa1, w4);
                    ffma2(s1[b + 5], qa1, w5);
                    ffma2(s1[b + 6], qa1, w6);
                }
            }
            qa0 = qb0; qa1 = qb1;
        }
        __syncthreads();  // done reading chunk before overwrite
    }

    // ================= reduce pairs + mask + scale + softmax =================
    const float scale = 0.17677669529663687f; // 1/sqrt(32)
    float p0s[KN], p1s[KN];
    float m0 = -1e30f, m1 = -1e30f;
    #pragma unroll
    for (int n = 0; n < KN; n++) {
        float lo, hi;
        unpack2(s0[n], lo, hi);
        float v0 = lo + hi;
        unpack2(s1[n], lo, hi);
        float v1 = lo + hi;
        const int dy = n / WIN - RAD;
        const int dx = n % WIN - RAD;
        const int gx = x + dx;
        const bool vx = (gx >= 0) & (gx < WS);
        const int gy0 = y0 + dy;
        const int gy1 = y1 + dy;
        const bool ok0 = vx & (gy0 >= 0) & (gy0 < HS);
        const bool ok1 = vx & (gy1 >= 0) & (gy1 < HS);
        p0s[n] = ok0 ? v0 * scale : -1e30f;
        p1s[n] = ok1 ? v1 * scale : -1e30f;
        m0 = fmaxf(m0, p0s[n]);
        m1 = fmaxf(m1, p1s[n]);
    }
    float sum0 = 0.0f, sum1 = 0.0f;
    #pragma unroll
    for (int n = 0; n < KN; n++) {
        p0s[n] = __expf(p0s[n] - m0);
        p1s[n] = __expf(p1s[n] - m1);
        sum0 += p0s[n];
        sum1 += p1s[n];
    }
    const float inv0 = 1.0f / sum0;
    const float inv1 = 1.0f / sum1;
    // re-pack probs broadcast as (p, p) into the s0/s1 ull arrays (reuse regs)
    #pragma unroll
    for (int n = 0; n < KN; n++) {
        float a = p0s[n] * inv0;
        float b = p1s[n] * inv1;
        s0[n] = pack2(a, a);
        s1[n] = pack2(b, b);
    }

    // ================= pass 2: output, channel-pair chunked =================
    #pragma unroll 1
    for (int cc = 0; cc < NCHUNK; cc++) {
        const int c0 = cc * 2 * CP;
        const float* vcc = vp + (size_t)c0 * HWs;

        #pragma unroll
        for (int p0 = 0; p0 < HALO_PIX; p0 += NTHR) {
            const int p = p0 + tid;
            if (p < HALO_PIX) {
                const int hy = p / HALO;
                const int hx = p - hy * HALO;
                const int gy = tileY0 + hy - RAD;
                const int gx = tileX0 + hx - RAD;
                const bool valid = (gy >= 0) & (gy < HS) & (gx >= 0) & (gx < WS);
                const int src = min(max(gy, 0), HS - 1) * WS + min(max(gx, 0), WS - 1);
                #pragma unroll
                for (int cpi = 0; cpi < CP; cpi++) {
                    float v0 = __ldg(vcc + (2 * cpi + 0) * HWs + src);
                    float v1 = __ldg(vcc + (2 * cpi + 1) * HWs + src);
                    sT[cpi][hy][hx] = valid ? make_float2(v0, v1)
                                            : make_float2(0.0f, 0.0f);
                }
            }
        }
        __syncthreads();

        #pragma unroll 1
        for (int cpi = 0; cpi < CP; cpi++) {
            const float2* vb = &sT[cpi][2 * typ][tx];
            ull a0 = 0, a1 = 0, a2 = 0, a3 = 0;   // px0 chains (lo=even ch, hi=odd)
            ull b0 = 0, b1 = 0, b2 = 0, b3 = 0;   // px1 chains
            #pragma unroll
            for (int r = 0; r < 8; r++) {
                const float2* wr = vb + r * HPAD2;
                ull w0 = *(const ull*)(wr + 0);
                ull w1 = *(const ull*)(wr + 1);
                ull w2 = *(const ull*)(wr + 2);
                ull w3 = *(const ull*)(wr + 3);
                ull w4 = *(const ull*)(wr + 4);
                ull w5 = *(const ull*)(wr + 5);
                ull w6 = *(const ull*)(wr + 6);
                if (r < 7) {
                    const int n = r * 7;
                    ffma2(a0, s0[n + 0], w0);
                    ffma2(a1, s0[n + 1], w1);
                    ffma2(a2, s0[n + 2], w2);
                    ffma2(a3, s0[n + 3], w3);
                    ffma2(a0, s0[n + 4], w4);
                    ffma2(a1, s0[n + 5], w5);
                    ffma2(a2, s0[n + 6], w6);
                }
                if (r > 0) {
                    const int n = (r - 1) * 7;
                    ffma2(b0, s1[n + 0], w0);
                    ffma2(b1, s1[n + 1], w1);
                    ffma2(b2, s1[n + 2], w2);
                    ffma2(b3, s1[n + 3], w3);
                    ffma2(b0, s1[n + 4], w4);
                    ffma2(b1, s1[n + 5], w5);
                    ffma2(b2, s1[n + 6], w6);
                }
            }
            ull ta = add2(add2(a0, a1), add2(a2, a3));
            ull tb = add2(add2(b0, b1), add2(b2, b3));
            float oa_e, oa_o, ob_e, ob_o;
            unpack2(ta, oa_e, oa_o);
            unpack2(tb, ob_e, ob_o);
            const int ce = c0 + 2 * cpi;
            op[ce * HWs + pix0]       = oa_e;
            op[(ce + 1) * HWs + pix0] = oa_o;
            op[ce * HWs + pix1]       = ob_e;
            op[(ce + 1) * HWs + pix1] = ob_o;
        }
        __syncthreads();
    }
}

extern "C" void kernel_launch(void* const* d_in, const int* in_sizes, int n_in,
                              void* d_out, int out_size)
{
    const float* q = (const float*)d_in[0];
    const float* k = (const float*)d_in[1];
    const float* v = (const float*)d_in[2];
    float* o = (float*)d_out;

    const int B = in_sizes[0] / (HEADS * DHEAD * HWs); // 4
    dim3 grid(WS / TILE, HS / TILE, B * HEADS);        // (3, 3, 32) = 288
    dim3 block(NTHR);                                  // 128 linear
    natten2d_kernel<<<grid, block>>>(q, k, v, o);
}